// round 16
// baseline (speedup 1.0000x reference)
#include <cuda_runtime.h>
#include <cuda_fp16.h>
#include <math.h>
#include <stdint.h>

#define BSZ 8192
#define EMB 256
#define INV_T (1.0f/0.07f)
#define GAMMAC 0.1f
#define EPSC 1e-10f

// A is pre-scaled by SCALE so acc = sim * SCALE and exp(sim/T) = exp2(acc).
#define SCALEF     20.609929155556625f   // (1/0.07) * log2(e)
#define INV_SCALEF 0.048520302639196164f // 1/SCALEF
#define SVOFF      5.0f                  // epilogue log2-shift (fp16 range safety)

// GEMM tiling: CTA 256x256, 512 threads (16 warps, 4x4 grid of 64x64 warp
// tiles), KC=64, 2-stage ring (128 KB), 1 CTA/SM, 16 warps/SM.
#define BM 256
#define BN 256
#define KC 64
#define NROWT (BSZ / BN)      // 32 row-partial strips
#define NCOLT (BSZ / BM)      // 32 col-partial strips
#define STAGEB 65536          // bytes per stage: A 32K + B 32K

#define NLOSSBLK 128          // 128 blocks x 256 thr; 2 threads per output

// ---- device scratch (static allocation; no runtime allocs) ----
__device__ __half gA16[(size_t)BSZ * EMB];   // fp16, pre-scaled by SCALEF
__device__ __half gB16[(size_t)BSZ * EMB];   // fp16
__device__ float g_rowPartE [(size_t)NROWT * BSZ];
__device__ float g_rowPartES[(size_t)NROWT * BSZ];
__device__ float g_colPartE [(size_t)NCOLT * BSZ];
__device__ float g_colPartES[(size_t)NCOLT * BSZ];
__device__ float g_diag[BSZ];
__device__ volatile float g_lossPart[NLOSSBLK];
__device__ unsigned g_lossTicket;            // zero-init; self-resets each launch

__device__ __forceinline__ __half2 h2ex2(__half2 x) {
    __half2 y;
    asm("ex2.approx.f16x2 %0, %1;"
        : "=r"(*reinterpret_cast<uint32_t*>(&y))
        : "r"(*reinterpret_cast<const uint32_t*>(&x)));
    return y;
}

__device__ __forceinline__ __half2 shfl_xor_h2(__half2 v, int o) {
    uint32_t u = __shfl_xor_sync(0xffffffffu, *reinterpret_cast<uint32_t*>(&v), o);
    return *reinterpret_cast<__half2*>(&u);
}

__device__ __forceinline__ void ldsm4(uint32_t r[4], uint32_t addr) {
    asm volatile("ldmatrix.sync.aligned.m8n8.x4.shared.b16 {%0,%1,%2,%3}, [%4];"
        : "=r"(r[0]), "=r"(r[1]), "=r"(r[2]), "=r"(r[3]) : "r"(addr));
}

// fp16-accumulate MMA (halves acc regs).
__device__ __forceinline__ void mma16816h(uint32_t c[2], const uint32_t a[4],
                                          uint32_t b0, uint32_t b1) {
    asm volatile(
        "mma.sync.aligned.m16n8k16.row.col.f16.f16.f16.f16 "
        "{%0,%1}, {%2,%3,%4,%5}, {%6,%7}, {%0,%1};"
        : "+r"(c[0]), "+r"(c[1])
        : "r"(a[0]), "r"(a[1]), "r"(a[2]), "r"(a[3]), "r"(b0), "r"(b1));
}

__device__ __forceinline__ uint32_t smem_u32(const void* p) {
    uint32_t a;
    asm("{ .reg .u64 t; cvta.to.shared.u64 t, %1; cvt.u32.u64 %0, t; }" : "=r"(a) : "l"(p));
    return a;
}

__device__ __forceinline__ void cpasync16(uint32_t dst, const void* src) {
    asm volatile("cp.async.cg.shared.global [%0], [%1], 16;" :: "r"(dst), "l"(src));
}
#define CP_COMMIT() asm volatile("cp.async.commit_group;" ::: "memory")
#define CP_WAIT(n)  asm volatile("cp.async.wait_group %0;" :: "n"(n) : "memory")

// ---------------------------------------------------------------------------
// Kernel 0: single-pass prep. One warp per row: read img+txt rows once,
// exact fp32 diag dot, write both fp16 rows (A scaled by SCALEF).
// ---------------------------------------------------------------------------
__global__ void __launch_bounds__(256) k_prep(
    const float* __restrict__ img, const float* __restrict__ txt)
{
    const int row  = blockIdx.x * 8 + (threadIdx.x >> 5);
    const int lane = threadIdx.x & 31;

    const float4* ap = reinterpret_cast<const float4*>(img + (size_t)row * EMB) + lane * 2;
    const float4* bp = reinterpret_cast<const float4*>(txt + (size_t)row * EMB) + lane * 2;
    float4 a0 = ap[0], a1 = ap[1];
    float4 b0 = bp[0], b1 = bp[1];

    float s = (a0.x*b0.x + a0.y*b0.y) + (a0.z*b0.z + a0.w*b0.w)
            + (a1.x*b1.x + a1.y*b1.y) + (a1.z*b1.z + a1.w*b1.w);
    #pragma unroll
    for (int o = 16; o; o >>= 1) s += __shfl_xor_sync(0xffffffffu, s, o);
    if (lane == 0) g_diag[row] = s;

    __half2 ha0 = __floats2half2_rn(a0.x * SCALEF, a0.y * SCALEF);
    __half2 ha1 = __floats2half2_rn(a0.z * SCALEF, a0.w * SCALEF);
    __half2 ha2 = __floats2half2_rn(a1.x * SCALEF, a1.y * SCALEF);
    __half2 ha3 = __floats2half2_rn(a1.z * SCALEF, a1.w * SCALEF);
    __half2 hb0 = __floats2half2_rn(b0.x, b0.y);
    __half2 hb1 = __floats2half2_rn(b0.z, b0.w);
    __half2 hb2 = __floats2half2_rn(b1.x, b1.y);
    __half2 hb3 = __floats2half2_rn(b1.z, b1.w);
    uint4 oa, ob;
    oa.x = *reinterpret_cast<uint32_t*>(&ha0);
    oa.y = *reinterpret_cast<uint32_t*>(&ha1);
    oa.z = *reinterpret_cast<uint32_t*>(&ha2);
    oa.w = *reinterpret_cast<uint32_t*>(&ha3);
    ob.x = *reinterpret_cast<uint32_t*>(&hb0);
    ob.y = *reinterpret_cast<uint32_t*>(&hb1);
    ob.z = *reinterpret_cast<uint32_t*>(&hb2);
    ob.w = *reinterpret_cast<uint32_t*>(&hb3);
    *reinterpret_cast<uint4*>(gA16 + (size_t)row * EMB + lane * 8) = oa;
    *reinterpret_cast<uint4*>(gB16 + (size_t)row * EMB + lane * 8) = ob;
}

// ---------------------------------------------------------------------------
// Kernel 1: fused fp16 GEMM (fp16 accum) + fp16 exp2 epilogue + partial sums.
// CTA tile 256x256, 512 threads, warp tile 64x64 (4x4), KC=64, 2-stage.
// ---------------------------------------------------------------------------
extern __shared__ char dsm[];

__global__ void __launch_bounds__(512, 1) k_gemm_fused()
{
    __shared__ float srowE[4][BM], srowES[4][BM];   // by wn group
    __shared__ float scolE[4][BN], scolES[4][BN];   // by wm group

    const int tid  = threadIdx.x;
    const int wid  = tid >> 5, lane = tid & 31;
    const int wm   = wid >> 2;          // 0..3 -> row offset wm*64
    const int wn   = wid & 3;           // 0..3 -> col offset wn*64
    const int kLane = lane & 3;
    const int bm   = blockIdx.y * BM, bn = blockIdx.x * BN;

    const uint32_t smemBase = smem_u32(dsm);

    uint32_t acc[4][8][2];              // half2 accumulators (64x64 warp tile)
    #pragma unroll
    for (int mt = 0; mt < 4; mt++)
        #pragma unroll
        for (int nt = 0; nt < 8; nt++) { acc[mt][nt][0] = 0u; acc[mt][nt][1] = 0u; }

    auto load_stage = [&](int c, int stage) {
        const int kt = c * KC;
        uint32_t sA = smemBase + stage * STAGEB;
        uint32_t sB = sA + 32768;
        #pragma unroll
        for (int i = 0; i < 4; i++) {
            int slot = tid + i * 512;           // 2048 slots: 256 rows x 8 chunks
            int row = slot >> 3, ch = slot & 7;
            uint32_t off = (row << 7) + ((ch ^ (row & 7)) << 4);
            cpasync16(sA + off, gA16 + (size_t)(bm + row) * EMB + kt + ch * 8);
        }
        #pragma unroll
        for (int i = 0; i < 4; i++) {
            int slot = tid + i * 512;
            int row = slot >> 3, ch = slot & 7;
            uint32_t off = (row << 7) + ((ch ^ (row & 7)) << 4);
            cpasync16(sB + off, gB16 + (size_t)(bn + row) * EMB + kt + ch * 8);
        }
        CP_COMMIT();
    };

    load_stage(0, 0);
    load_stage(1, 1);

    #pragma unroll
    for (int c = 0; c < EMB / KC; c++) {
        if (c < EMB / KC - 1) CP_WAIT(1); else CP_WAIT(0);
        __syncthreads();
        const uint32_t aBase = smemBase + (c & 1) * STAGEB;
        const uint32_t bBase = aBase + 32768;

        #pragma unroll
        for (int ks = 0; ks < 4; ks++) {
            uint32_t a[4][4];
            #pragma unroll
            for (int mt = 0; mt < 4; mt++) {
                int row = wm * 64 + mt * 16 + (lane & 15);
                int ch  = ks * 2 + (lane >> 4);
                ldsm4(a[mt], aBase + (row << 7) + ((ch ^ (row & 7)) << 4));
            }
            uint32_t bb[4][4];
            #pragma unroll
            for (int p = 0; p < 4; p++) {
                int row = wn * 64 + p * 16 + ((lane >> 4) << 3) + (lane & 7);
                int ch  = ks * 2 + ((lane >> 3) & 1);
                ldsm4(bb[p], bBase + (row << 7) + ((ch ^ (row & 7)) << 4));
            }
            #pragma unroll
            for (int mt = 0; mt < 4; mt++)
                #pragma unroll
                for (int p = 0; p < 4; p++) {
                    mma16816h(acc[mt][2 * p],     a[mt], bb[p][0], bb[p][1]);
                    mma16816h(acc[mt][2 * p + 1], a[mt], bb[p][2], bb[p][3]);
                }
        }
        if (c + 2 < EMB / KC) {
            __syncthreads();
            load_stage(c + 2, c & 1);
        }
    }

    // ---- epilogue (all fp16): a' = acc - 5; E = exp2(a'); sums of E, E*a' ----
    const __half2 h5 = __floats2half2_rn(SVOFF, SVOFF);
    const __half2 hz = __floats2half2_rn(0.f, 0.f);
    __half2 rE2[4][2], rES2[4][2];
    #pragma unroll
    for (int mt = 0; mt < 4; mt++)
        #pragma unroll
        for (int h = 0; h < 2; h++) { rE2[mt][h] = hz; rES2[mt][h] = hz; }

    #pragma unroll
    for (int nt = 0; nt < 8; nt++) {
        __half2 cE2 = hz, cES2 = hz;
        #pragma unroll
        for (int mt = 0; mt < 4; mt++) {
            __half2 a0 = __hsub2(*reinterpret_cast<__half2*>(&acc[mt][nt][0]), h5);
            __half2 a1 = __hsub2(*reinterpret_cast<__half2*>(&acc[mt][nt][1]), h5);
            __half2 e0 = h2ex2(a0);
            __half2 e1 = h2ex2(a1);
            rE2 [mt][0] = __hadd2(rE2[mt][0], e0);
            rE2 [mt][1] = __hadd2(rE2[mt][1], e1);
            rES2[mt][0] = __hfma2(e0, a0, rES2[mt][0]);
            rES2[mt][1] = __hfma2(e1, a1, rES2[mt][1]);
            cE2  = __hadd2(cE2, __hadd2(e0, e1));
            cES2 = __hfma2(e0, a0, __hfma2(e1, a1, cES2));
        }
        #pragma unroll
        for (int o = 4; o <= 16; o <<= 1) {
            cE2  = __hadd2(cE2,  shfl_xor_h2(cE2,  o));
            cES2 = __hadd2(cES2, shfl_xor_h2(cES2, o));
        }
        if (lane < 4) {
            float2 vE = __half22float2(cE2);
            float2 vS = __half22float2(cES2);
            int cl = wn * 64 + nt * 8 + 2 * lane;
            scolE [wm][cl]     = vE.x;
            scolE [wm][cl + 1] = vE.y;
            scolES[wm][cl]     = vS.x;
            scolES[wm][cl + 1] = vS.y;
        }
    }
    #pragma unroll
    for (int mt = 0; mt < 4; mt++)
        #pragma unroll
        for (int h = 0; h < 2; h++)
            #pragma unroll
            for (int o = 1; o <= 2; o <<= 1) {
                rE2 [mt][h] = __hadd2(rE2 [mt][h], shfl_xor_h2(rE2 [mt][h], o));
                rES2[mt][h] = __hadd2(rES2[mt][h], shfl_xor_h2(rES2[mt][h], o));
            }
    if (kLane == 0) {
        #pragma unroll
        for (int mt = 0; mt < 4; mt++)
            #pragma unroll
            for (int h = 0; h < 2; h++) {
                int rl = wm * 64 + mt * 16 + h * 8 + (lane >> 2);
                float2 v = __half22float2(rE2 [mt][h]);
                float2 w = __half22float2(rES2[mt][h]);
                srowE [wn][rl] = v.x + v.y;
                srowES[wn][rl] = w.x + w.y;
            }
    }
    __syncthreads();

    if (tid < BM) {      // row partials (256 rows): sum 4 wn groups
        size_t idx = (size_t)blockIdx.x * BSZ + bm + tid;
        g_rowPartE [idx] = (srowE [0][tid] + srowE [1][tid]) + (srowE [2][tid] + srowE [3][tid]);
        g_rowPartES[idx] = ((srowES[0][tid] + srowES[1][tid]) + (srowES[2][tid] + srowES[3][tid]))
                           * INV_SCALEF;
    } else {             // col partials (256 cols): sum 4 wm groups
        int t = tid - BM;
        size_t idx = (size_t)blockIdx.y * BSZ + bn + t;
        g_colPartE [idx] = (scolE [0][t] + scolE [1][t]) + (scolE [2][t] + scolE [3][t]);
        g_colPartES[idx] = ((scolES[0][t] + scolES[1][t]) + (scolES[2][t] + scolES[3][t]))
                           * INV_SCALEF;
    }
}

// ---------------------------------------------------------------------------
// Kernel 2: losses, TWO threads per output (coalesced). 32 strips each side;
// each half-thread sums 16. Partner combine via shfl_xor(1); last-ticket
// block reduces the 128 block partials. Fixed order -> deterministic.
// ---------------------------------------------------------------------------
__global__ void __launch_bounds__(256) k_loss(
    const float* __restrict__ s_I, const float* __restrict__ s_T,
    const int* __restrict__ iid, const int* __restrict__ tid_,
    float* __restrict__ out)
{
    const int g    = blockIdx.x * 256 + threadIdx.x;  // 0 .. 32767
    const int o    = g >> 1;                          // output 0 .. 16383
    const int half = g & 1;
    const bool isRow = o < BSZ;
    const int i    = isRow ? o : o - BSZ;
    const float* pE  = isRow ? g_rowPartE  : g_colPartE;
    const float* pES = isRow ? g_rowPartES : g_colPartES;

    const int kStart = half * 16;
    float sumE = 0.f, sumES = 0.f;
    #pragma unroll 8
    for (int k = kStart; k < kStart + 16; k++) {
        sumE  += pE [(size_t)k * BSZ + i];
        sumES += pES[(size_t)k * BSZ + i];
    }
    sumE  += __shfl_xor_sync(0xffffffffu, sumE,  1);
    sumES += __shfl_xor_sync(0xffffffffu, sumES, 1);

    __shared__ float sl[256];
    __shared__ bool sLast;
    float loss = 0.f;
    if (half == 0) {
        sumES += (SVOFF * INV_SCALEF) * sumE;   // undo epilogue log2 shift
        float d = g_diag[i];
        float f = __expf(-d * INV_T);
        float Se  = f * sumE;
        float Sed = f * (sumES - d * sumE);
        const float invBm1 = 1.0f / (float)(BSZ - 1);
        float gv = Se * invBm1;
        float sOld = isRow ? s_I[iid[i]] : s_T[tid_[i]];
        float sNew = (1.0f - GAMMAC) * sOld + GAMMAC * gv;
        loss = (Sed * invBm1) / (sNew + EPSC);
    }
    sl[threadIdx.x] = loss;
    __syncthreads();
    #pragma unroll
    for (int off = 128; off; off >>= 1) {
        if (threadIdx.x < off) sl[threadIdx.x] += sl[threadIdx.x + off];
        __syncthreads();
    }
    if (threadIdx.x == 0) {
        g_lossPart[blockIdx.x] = sl[0];
        __threadfence();
        unsigned done = atomicAdd(&g_lossTicket, 1u);
        sLast = (done == NLOSSBLK - 1);
    }
    __syncthreads();
    if (sLast) {
        __threadfence();
        float v = (threadIdx.x < NLOSSBLK) ? g_lossPart[threadIdx.x] : 0.f;
        sl[threadIdx.x] = v;
        __syncthreads();
        #pragma unroll
        for (int off = 128; off; off >>= 1) {
            if (threadIdx.x < off) sl[threadIdx.x] += sl[threadIdx.x + off];
            __syncthreads();
        }
        if (threadIdx.x == 0) {
            out[0] = sl[0] / (float)BSZ;
            g_lossTicket = 0u;            // reset for next graph replay
        }
    }
}

// ---------------------------------------------------------------------------
extern "C" void kernel_launch(void* const* d_in, const int* in_sizes, int n_in,
                              void* d_out, int out_size)
{
    const float* img = (const float*)d_in[0];
    const float* txt = (const float*)d_in[1];
    const float* s_I = (const float*)d_in[4];
    const float* s_T = (const float*)d_in[5];
    const int*   iid = (const int*)d_in[6];
    const int*   tid = (const int*)d_in[7];

    static bool attrDone = false;
    if (!attrDone) {
        cudaFuncSetAttribute(k_gemm_fused,
                             cudaFuncAttributeMaxDynamicSharedMemorySize, 2 * STAGEB);
        attrDone = true;
    }

    k_prep<<<BSZ / 8, 256>>>(img, txt);          // warp per row
    dim3 g(BSZ / BN, BSZ / BM);                  // 32 x 32 tiles
    k_gemm_fused<<<g, 512, 2 * STAGEB>>>();
    k_loss<<<NLOSSBLK, 256>>>(s_I, s_T, iid, tid, (float*)d_out);
}

// round 17
// speedup vs baseline: 1.0417x; 1.0417x over previous
#include <cuda_runtime.h>
#include <cuda_fp16.h>
#include <math.h>
#include <stdint.h>

#define BSZ 8192
#define EMB 256
#define INV_T (1.0f/0.07f)
#define GAMMAC 0.1f
#define EPSC 1e-10f

// A is pre-scaled by SCALE so acc = sim * SCALE and exp(sim/T) = exp2(acc).
#define SCALEF     20.609929155556625f   // (1/0.07) * log2(e)
#define INV_SCALEF 0.048520302639196164f // 1/SCALEF
#define SVOFF      5.0f                  // epilogue log2-shift (fp16 range safety)

// GEMM tiling: CTA 256x128, 8 warps (warp tile 64x64), KC=64, 2-stage ring,
// 2 CTAs/SM for cross-CTA prologue/epilogue overlap. (R13/R15 proven config)
#define BM 256
#define BN 128
#define KC 64
#define NROWT (BSZ / BN)      // 64 row-partial strips
#define NCOLT (BSZ / BM)      // 32 col-partial strips
#define STAGEB 49152          // bytes per stage: A 32K + B 16K

#define NLOSSBLK 256          // 256 blocks x 256 thr; 4 threads per output

// ---- device scratch (static allocation; no runtime allocs) ----
__device__ __half gA16[(size_t)BSZ * EMB];   // fp16, pre-scaled by SCALEF
__device__ __half gB16[(size_t)BSZ * EMB];   // fp16
__device__ float g_rowPartE [(size_t)NROWT * BSZ];
__device__ float g_rowPartES[(size_t)NROWT * BSZ];
__device__ float g_colPartE [(size_t)NCOLT * BSZ];
__device__ float g_colPartES[(size_t)NCOLT * BSZ];
__device__ float g_diag[BSZ];
__device__ volatile float g_lossPart[NLOSSBLK];
__device__ unsigned g_lossTicket;            // zero-init; self-resets each launch

__device__ __forceinline__ __half2 h2ex2(__half2 x) {
    __half2 y;
    asm("ex2.approx.f16x2 %0, %1;"
        : "=r"(*reinterpret_cast<uint32_t*>(&y))
        : "r"(*reinterpret_cast<const uint32_t*>(&x)));
    return y;
}

__device__ __forceinline__ __half2 shfl_xor_h2(__half2 v, int o) {
    uint32_t u = __shfl_xor_sync(0xffffffffu, *reinterpret_cast<uint32_t*>(&v), o);
    return *reinterpret_cast<__half2*>(&u);
}

__device__ __forceinline__ void ldsm4(uint32_t r[4], uint32_t addr) {
    asm volatile("ldmatrix.sync.aligned.m8n8.x4.shared.b16 {%0,%1,%2,%3}, [%4];"
        : "=r"(r[0]), "=r"(r[1]), "=r"(r[2]), "=r"(r[3]) : "r"(addr));
}

// fp16-accumulate MMA (halves acc regs -> enables 2 CTAs/SM).
__device__ __forceinline__ void mma16816h(uint32_t c[2], const uint32_t a[4],
                                          uint32_t b0, uint32_t b1) {
    asm volatile(
        "mma.sync.aligned.m16n8k16.row.col.f16.f16.f16.f16 "
        "{%0,%1}, {%2,%3,%4,%5}, {%6,%7}, {%0,%1};"
        : "+r"(c[0]), "+r"(c[1])
        : "r"(a[0]), "r"(a[1]), "r"(a[2]), "r"(a[3]), "r"(b0), "r"(b1));
}

__device__ __forceinline__ uint32_t smem_u32(const void* p) {
    uint32_t a;
    asm("{ .reg .u64 t; cvta.to.shared.u64 t, %1; cvt.u32.u64 %0, t; }" : "=r"(a) : "l"(p));
    return a;
}

__device__ __forceinline__ void cpasync16(uint32_t dst, const void* src) {
    asm volatile("cp.async.cg.shared.global [%0], [%1], 16;" :: "r"(dst), "l"(src));
}
#define CP_COMMIT() asm volatile("cp.async.commit_group;" ::: "memory")
#define CP_WAIT(n)  asm volatile("cp.async.wait_group %0;" :: "n"(n) : "memory")

// ---------------------------------------------------------------------------
// Kernel 0: single-pass prep. One warp per row: read img+txt rows once,
// exact fp32 diag dot, write both fp16 rows (A scaled by SCALEF).
// ---------------------------------------------------------------------------
__global__ void __launch_bounds__(256) k_prep(
    const float* __restrict__ img, const float* __restrict__ txt)
{
    const int row  = blockIdx.x * 8 + (threadIdx.x >> 5);
    const int lane = threadIdx.x & 31;

    const float4* ap = reinterpret_cast<const float4*>(img + (size_t)row * EMB) + lane * 2;
    const float4* bp = reinterpret_cast<const float4*>(txt + (size_t)row * EMB) + lane * 2;
    float4 a0 = ap[0], a1 = ap[1];
    float4 b0 = bp[0], b1 = bp[1];

    float s = (a0.x*b0.x + a0.y*b0.y) + (a0.z*b0.z + a0.w*b0.w)
            + (a1.x*b1.x + a1.y*b1.y) + (a1.z*b1.z + a1.w*b1.w);
    #pragma unroll
    for (int o = 16; o; o >>= 1) s += __shfl_xor_sync(0xffffffffu, s, o);
    if (lane == 0) g_diag[row] = s;

    __half2 ha0 = __floats2half2_rn(a0.x * SCALEF, a0.y * SCALEF);
    __half2 ha1 = __floats2half2_rn(a0.z * SCALEF, a0.w * SCALEF);
    __half2 ha2 = __floats2half2_rn(a1.x * SCALEF, a1.y * SCALEF);
    __half2 ha3 = __floats2half2_rn(a1.z * SCALEF, a1.w * SCALEF);
    __half2 hb0 = __floats2half2_rn(b0.x, b0.y);
    __half2 hb1 = __floats2half2_rn(b0.z, b0.w);
    __half2 hb2 = __floats2half2_rn(b1.x, b1.y);
    __half2 hb3 = __floats2half2_rn(b1.z, b1.w);
    uint4 oa, ob;
    oa.x = *reinterpret_cast<uint32_t*>(&ha0);
    oa.y = *reinterpret_cast<uint32_t*>(&ha1);
    oa.z = *reinterpret_cast<uint32_t*>(&ha2);
    oa.w = *reinterpret_cast<uint32_t*>(&ha3);
    ob.x = *reinterpret_cast<uint32_t*>(&hb0);
    ob.y = *reinterpret_cast<uint32_t*>(&hb1);
    ob.z = *reinterpret_cast<uint32_t*>(&hb2);
    ob.w = *reinterpret_cast<uint32_t*>(&hb3);
    *reinterpret_cast<uint4*>(gA16 + (size_t)row * EMB + lane * 8) = oa;
    *reinterpret_cast<uint4*>(gB16 + (size_t)row * EMB + lane * 8) = ob;
}

// ---------------------------------------------------------------------------
// Kernel 1: fused fp16 GEMM (fp16 accum) + fp16 exp2 epilogue + partial sums.
// CTA tile 256x128, 8 warps (warp tile 64x64), KC=64, 2-stage, 2 CTAs/SM.
// (byte-for-byte the R13/R15 proven winner)
// ---------------------------------------------------------------------------
extern __shared__ char dsm[];

__global__ void __launch_bounds__(256, 2) k_gemm_fused()
{
    __shared__ float srowE[2][BM], srowES[2][BM];
    __shared__ float scolE[4][BN], scolES[4][BN];

    const int tid  = threadIdx.x;
    const int wid  = tid >> 5, lane = tid & 31;
    const int wm   = wid >> 1;          // 0..3 -> row offset wm*64
    const int wn   = wid & 1;           // 0..1 -> col offset wn*64
    const int kLane = lane & 3;
    const int bm   = blockIdx.y * BM, bn = blockIdx.x * BN;

    const uint32_t smemBase = smem_u32(dsm);

    uint32_t acc[4][8][2];              // half2 accumulators
    #pragma unroll
    for (int mt = 0; mt < 4; mt++)
        #pragma unroll
        for (int nt = 0; nt < 8; nt++) { acc[mt][nt][0] = 0u; acc[mt][nt][1] = 0u; }

    auto load_stage = [&](int c, int stage) {
        const int kt = c * KC;
        uint32_t sA = smemBase + stage * STAGEB;
        uint32_t sB = sA + 32768;
        #pragma unroll
        for (int i = 0; i < 8; i++) {
            int slot = tid + i * 256;
            int row = slot >> 3, ch = slot & 7;
            uint32_t off = (row << 7) + ((ch ^ (row & 7)) << 4);
            cpasync16(sA + off, gA16 + (size_t)(bm + row) * EMB + kt + ch * 8);
        }
        #pragma unroll
        for (int i = 0; i < 4; i++) {
            int slot = tid + i * 256;
            int row = slot >> 3, ch = slot & 7;
            uint32_t off = (row << 7) + ((ch ^ (row & 7)) << 4);
            cpasync16(sB + off, gB16 + (size_t)(bn + row) * EMB + kt + ch * 8);
        }
        CP_COMMIT();
    };

    load_stage(0, 0);
    load_stage(1, 1);

    #pragma unroll
    for (int c = 0; c < EMB / KC; c++) {
        if (c < EMB / KC - 1) CP_WAIT(1); else CP_WAIT(0);
        __syncthreads();
        const uint32_t aBase = smemBase + (c & 1) * STAGEB;
        const uint32_t bBase = aBase + 32768;

        #pragma unroll
        for (int ks = 0; ks < 4; ks++) {
            uint32_t a[4][4];
            #pragma unroll
            for (int mt = 0; mt < 4; mt++) {
                int row = wm * 64 + mt * 16 + (lane & 15);
                int ch  = ks * 2 + (lane >> 4);
                ldsm4(a[mt], aBase + (row << 7) + ((ch ^ (row & 7)) << 4));
            }
            uint32_t bb[4][4];
            #pragma unroll
            for (int p = 0; p < 4; p++) {
                int row = wn * 64 + p * 16 + ((lane >> 4) << 3) + (lane & 7);
                int ch  = ks * 2 + ((lane >> 3) & 1);
                ldsm4(bb[p], bBase + (row << 7) + ((ch ^ (row & 7)) << 4));
            }
            #pragma unroll
            for (int mt = 0; mt < 4; mt++)
                #pragma unroll
                for (int p = 0; p < 4; p++) {
                    mma16816h(acc[mt][2 * p],     a[mt], bb[p][0], bb[p][1]);
                    mma16816h(acc[mt][2 * p + 1], a[mt], bb[p][2], bb[p][3]);
                }
        }
        if (c + 2 < EMB / KC) {
            __syncthreads();
            load_stage(c + 2, c & 1);
        }
    }

    // ---- epilogue (all fp16): a' = acc - 5; E = exp2(a'); sums of E, E*a' ----
    const __half2 h5 = __floats2half2_rn(SVOFF, SVOFF);
    const __half2 hz = __floats2half2_rn(0.f, 0.f);
    __half2 rE2[4][2], rES2[4][2];
    #pragma unroll
    for (int mt = 0; mt < 4; mt++)
        #pragma unroll
        for (int h = 0; h < 2; h++) { rE2[mt][h] = hz; rES2[mt][h] = hz; }

    #pragma unroll
    for (int nt = 0; nt < 8; nt++) {
        __half2 cE2 = hz, cES2 = hz;
        #pragma unroll
        for (int mt = 0; mt < 4; mt++) {
            __half2 a0 = __hsub2(*reinterpret_cast<__half2*>(&acc[mt][nt][0]), h5);
            __half2 a1 = __hsub2(*reinterpret_cast<__half2*>(&acc[mt][nt][1]), h5);
            __half2 e0 = h2ex2(a0);
            __half2 e1 = h2ex2(a1);
            rE2 [mt][0] = __hadd2(rE2[mt][0], e0);
            rE2 [mt][1] = __hadd2(rE2[mt][1], e1);
            rES2[mt][0] = __hfma2(e0, a0, rES2[mt][0]);
            rES2[mt][1] = __hfma2(e1, a1, rES2[mt][1]);
            cE2  = __hadd2(cE2, __hadd2(e0, e1));
            cES2 = __hfma2(e0, a0, __hfma2(e1, a1, cES2));
        }
        #pragma unroll
        for (int o = 4; o <= 16; o <<= 1) {
            cE2  = __hadd2(cE2,  shfl_xor_h2(cE2,  o));
            cES2 = __hadd2(cES2, shfl_xor_h2(cES2, o));
        }
        if (lane < 4) {
            float2 vE = __half22float2(cE2);
            float2 vS = __half22float2(cES2);
            int cl = wn * 64 + nt * 8 + 2 * lane;
            scolE [wm][cl]     = vE.x;
            scolE [wm][cl + 1] = vE.y;
            scolES[wm][cl]     = vS.x;
            scolES[wm][cl + 1] = vS.y;
        }
    }
    #pragma unroll
    for (int mt = 0; mt < 4; mt++)
        #pragma unroll
        for (int h = 0; h < 2; h++)
            #pragma unroll
            for (int o = 1; o <= 2; o <<= 1) {
                rE2 [mt][h] = __hadd2(rE2 [mt][h], shfl_xor_h2(rE2 [mt][h], o));
                rES2[mt][h] = __hadd2(rES2[mt][h], shfl_xor_h2(rES2[mt][h], o));
            }
    if (kLane == 0) {
        #pragma unroll
        for (int mt = 0; mt < 4; mt++)
            #pragma unroll
            for (int h = 0; h < 2; h++) {
                int rl = wm * 64 + mt * 16 + h * 8 + (lane >> 2);
                float2 v = __half22float2(rE2 [mt][h]);
                float2 w = __half22float2(rES2[mt][h]);
                srowE [wn][rl] = v.x + v.y;
                srowES[wn][rl] = w.x + w.y;
            }
    }
    __syncthreads();

    {   // row partials (256 rows); ES stays in shifted log2 units * INV_SCALEF
        size_t idx = (size_t)blockIdx.x * BSZ + bm + tid;
        g_rowPartE [idx] = srowE [0][tid] + srowE [1][tid];
        g_rowPartES[idx] = (srowES[0][tid] + srowES[1][tid]) * INV_SCALEF;
    }
    if (tid < BN) {   // col partials (128 cols)
        size_t idx = (size_t)blockIdx.y * BSZ + bn + tid;
        g_colPartE [idx] = (scolE [0][tid] + scolE [1][tid]) + (scolE [2][tid] + scolE [3][tid]);
        g_colPartES[idx] = ((scolES[0][tid] + scolES[1][tid]) + (scolES[2][tid] + scolES[3][tid]))
                           * INV_SCALEF;
    }
}

// ---------------------------------------------------------------------------
// Kernel 2: losses, FOUR threads per output (coalesced: thread->output along
// i, iteration->strip). Quarters combined via shfl_xor(1), shfl_xor(2).
// Last-ticket block reduces the 256 block partials (one per thread).
// Fixed order -> deterministic.
// ---------------------------------------------------------------------------
__global__ void __launch_bounds__(256) k_loss(
    const float* __restrict__ s_I, const float* __restrict__ s_T,
    const int* __restrict__ iid, const int* __restrict__ tid_,
    float* __restrict__ out)
{
    const int g    = blockIdx.x * 256 + threadIdx.x;  // 0 .. 65535
    const int o    = g >> 2;                          // output 0 .. 16383
    const int quad = g & 3;
    const bool isRow = o < BSZ;
    const int i    = isRow ? o : o - BSZ;
    const float* pE  = isRow ? g_rowPartE  : g_colPartE;
    const float* pES = isRow ? g_rowPartES : g_colPartES;

    const int kCnt   = isRow ? 16 : 8;          // 64 or 32 strips over 4 threads
    const int kStart = quad * kCnt;
    float sumE = 0.f, sumES = 0.f;
    #pragma unroll 8
    for (int k = kStart; k < kStart + kCnt; k++) {
        sumE  += pE [(size_t)k * BSZ + i];
        sumES += pES[(size_t)k * BSZ + i];
    }
    // combine quarters (lanes 4t..4t+3 hold the same output)
    sumE  += __shfl_xor_sync(0xffffffffu, sumE,  1);
    sumES += __shfl_xor_sync(0xffffffffu, sumES, 1);
    sumE  += __shfl_xor_sync(0xffffffffu, sumE,  2);
    sumES += __shfl_xor_sync(0xffffffffu, sumES, 2);

    __shared__ float sl[256];
    __shared__ bool sLast;
    float loss = 0.f;
    if (quad == 0) {
        sumES += (SVOFF * INV_SCALEF) * sumE;   // undo epilogue log2 shift
        float d = g_diag[i];
        float f = __expf(-d * INV_T);
        float Se  = f * sumE;
        float Sed = f * (sumES - d * sumE);
        const float invBm1 = 1.0f / (float)(BSZ - 1);
        float gv = Se * invBm1;
        float sOld = isRow ? s_I[iid[i]] : s_T[tid_[i]];
        float sNew = (1.0f - GAMMAC) * sOld + GAMMAC * gv;
        loss = (Sed * invBm1) / (sNew + EPSC);
    }
    sl[threadIdx.x] = loss;                     // quads 1-3 contribute 0
    __syncthreads();
    #pragma unroll
    for (int off = 128; off; off >>= 1) {
        if (threadIdx.x < off) sl[threadIdx.x] += sl[threadIdx.x + off];
        __syncthreads();
    }
    if (threadIdx.x == 0) {
        g_lossPart[blockIdx.x] = sl[0];
        __threadfence();
        unsigned done = atomicAdd(&g_lossTicket, 1u);
        sLast = (done == NLOSSBLK - 1);
    }
    __syncthreads();
    if (sLast) {
        __threadfence();
        sl[threadIdx.x] = g_lossPart[threadIdx.x];   // NLOSSBLK == 256
        __syncthreads();
        #pragma unroll
        for (int off = 128; off; off >>= 1) {
            if (threadIdx.x < off) sl[threadIdx.x] += sl[threadIdx.x + off];
            __syncthreads();
        }
        if (threadIdx.x == 0) {
            out[0] = sl[0] / (float)BSZ;
            g_lossTicket = 0u;            // reset for next graph replay
        }
    }
}

// ---------------------------------------------------------------------------
extern "C" void kernel_launch(void* const* d_in, const int* in_sizes, int n_in,
                              void* d_out, int out_size)
{
    const float* img = (const float*)d_in[0];
    const float* txt = (const float*)d_in[1];
    const float* s_I = (const float*)d_in[4];
    const float* s_T = (const float*)d_in[5];
    const int*   iid = (const int*)d_in[6];
    const int*   tid = (const int*)d_in[7];

    static bool attrDone = false;
    if (!attrDone) {
        cudaFuncSetAttribute(k_gemm_fused,
                             cudaFuncAttributeMaxDynamicSharedMemorySize, 2 * STAGEB);
        attrDone = true;
    }

    k_prep<<<BSZ / 8, 256>>>(img, txt);          // warp per row
    dim3 g(BSZ / BN, BSZ / BM);
    k_gemm_fused<<<g, 256, 2 * STAGEB>>>();
    k_loss<<<NLOSSBLK, 256>>>(s_I, s_T, iid, tid, (float*)d_out);
}